// round 1
// baseline (speedup 1.0000x reference)
#include <cuda_runtime.h>
#include <cuda_bf16.h>
#include <math.h>

// Problem constants (fixed by setup_inputs)
#define BATCH   2048
#define DDIM    32
#define CDIM    128
#define HID     512
#define INRAW   161           // D + 1 + C
#define INPAD   176           // padded to multiple of 16 for BK loop
#define NSTEPS  16

// ---------------- device scratch (no allocations allowed) ----------------
__device__ float g_xbuf [BATCH * INPAD];     // [theta(32), t, context(128), pad(15)]
__device__ float g_h1   [BATCH * HID];
__device__ float g_h2   [BATCH * HID];
__device__ float g_theta[BATCH * DDIM];
__device__ float g_ksum [BATCH * DDIM];
__device__ float g_W1p  [INPAD * 2 * HID];   // zero-padded W1 rows

// ---------------- init kernels ----------------
__global__ void init_pad_w1(const float* __restrict__ W1) {
    int idx = blockIdx.x * blockDim.x + threadIdx.x;
    if (idx < INPAD * 1024) {
        int r = idx >> 10;
        g_W1p[idx] = (r < INRAW) ? W1[idx] : 0.0f;  // same linear layout for r<161
    }
}

__global__ void init_x(const float* __restrict__ theta0,
                       const float* __restrict__ context) {
    int r = blockIdx.x;
    int t = threadIdx.x;           // blockDim = 192
    if (t < DDIM) {
        float v = theta0[r * DDIM + t];
        g_xbuf[r * INPAD + t] = v;
        g_theta[r * DDIM + t] = v;
    } else if (t == DDIM) {
        g_xbuf[r * INPAD + DDIM] = 0.0f;               // t = 0
    } else if (t < INRAW) {
        g_xbuf[r * INPAD + t] = context[r * CDIM + (t - DDIM - 1)];
    } else if (t < INPAD) {
        g_xbuf[r * INPAD + t] = 0.0f;                  // K padding
    }
}

// ---------------- fused GEMM + GLU ----------------
// out[m, n] = (sum_k A[m,k] * W[k,n]      + bias[n])
//           * sigmoid(sum_k A[m,k] * W[k,n+512] + bias[n+512])
// A: [M, lda] row-major, W: [K, 1024] row-major, out: [M, 512] row-major.
// BM=128, BN=64 (per half), BK=16; 256 threads; each thread 8x4 per half.
#define BM 128
#define BN 64
#define BK 16

__global__ __launch_bounds__(256)
void glu_gemm(const float* __restrict__ A, int lda, int K,
              const float* __restrict__ W, const float* __restrict__ bias,
              float* __restrict__ out) {
    __shared__ float As [BK][BM + 4];   // k-major, padded vs bank conflicts
    __shared__ float Was[BK][BN];
    __shared__ float Wbs[BK][BN];

    const int tid = threadIdx.x;
    const int tx = tid & 15;            // 0..15 -> 64 cols
    const int ty = tid >> 4;            // 0..15 -> 128 rows
    const int bm = blockIdx.y * BM;
    const int bn = blockIdx.x * BN;

    float acc_a[8][4];
    float acc_b[8][4];
#pragma unroll
    for (int i = 0; i < 8; ++i)
#pragma unroll
        for (int j = 0; j < 4; ++j) { acc_a[i][j] = 0.f; acc_b[i][j] = 0.f; }

    for (int k0 = 0; k0 < K; k0 += BK) {
        // load A tile: 128x16 floats = 512 float4, 2 per thread
#pragma unroll
        for (int p = 0; p < 2; ++p) {
            int slot = tid + p * 256;
            int row  = slot >> 2;          // 0..127
            int kq   = (slot & 3) * 4;     // 0,4,8,12
            float4 v = *reinterpret_cast<const float4*>(
                &A[(size_t)(bm + row) * lda + k0 + kq]);
            As[kq + 0][row] = v.x;
            As[kq + 1][row] = v.y;
            As[kq + 2][row] = v.z;
            As[kq + 3][row] = v.w;
        }
        // load W tiles (a- and b-half): 16x64 each, 1 float4 per thread per half
        {
            int krow = tid >> 4;           // 0..15
            int cq   = (tid & 15) * 4;     // 0..60
            const float* wp = &W[(size_t)(k0 + krow) * 1024 + bn + cq];
            float4 va = *reinterpret_cast<const float4*>(wp);
            float4 vb = *reinterpret_cast<const float4*>(wp + HID);
            *reinterpret_cast<float4*>(&Was[krow][cq]) = va;
            *reinterpret_cast<float4*>(&Wbs[krow][cq]) = vb;
        }
        __syncthreads();

#pragma unroll
        for (int kk = 0; kk < BK; ++kk) {
            float4 a0 = *reinterpret_cast<const float4*>(&As[kk][ty * 8]);
            float4 a1 = *reinterpret_cast<const float4*>(&As[kk][ty * 8 + 4]);
            float4 w4a = *reinterpret_cast<const float4*>(&Was[kk][tx * 4]);
            float4 w4b = *reinterpret_cast<const float4*>(&Wbs[kk][tx * 4]);
            float a[8]  = {a0.x, a0.y, a0.z, a0.w, a1.x, a1.y, a1.z, a1.w};
            float wa[4] = {w4a.x, w4a.y, w4a.z, w4a.w};
            float wb[4] = {w4b.x, w4b.y, w4b.z, w4b.w};
#pragma unroll
            for (int i = 0; i < 8; ++i)
#pragma unroll
                for (int j = 0; j < 4; ++j) {
                    acc_a[i][j] = fmaf(a[i], wa[j], acc_a[i][j]);
                    acc_b[i][j] = fmaf(a[i], wb[j], acc_b[i][j]);
                }
        }
        __syncthreads();
    }

    // epilogue: GLU
#pragma unroll
    for (int i = 0; i < 8; ++i) {
        int row = bm + ty * 8 + i;
        float4 o;
        float* ov = (float*)&o;
#pragma unroll
        for (int j = 0; j < 4; ++j) {
            int col = bn + tx * 4 + j;
            float av = acc_a[i][j] + bias[col];
            float bv = acc_b[i][j] + bias[HID + col];
            float s  = 1.0f / (1.0f + __expf(-bv));
            ov[j] = av * s;
        }
        *reinterpret_cast<float4*>(&out[(size_t)row * HID + bn + tx * 4]) = o;
    }
}

// ---------------- layer 3 + RK4 stage update ----------------
// One warp per batch row: k = h2[row,:] @ W3 + b3  (lane = output dim, D=32)
// then RK4 stage bookkeeping + write next-stage xbuf.
__global__ __launch_bounds__(256)
void k3_update(const float* __restrict__ W3, const float* __restrict__ b3,
               int stage, float t_next, float dt,
               float* __restrict__ final_out) {
    __shared__ float ws[32][33];
    const int tid  = threadIdx.x;
    const int lane = tid & 31;
    const int w    = tid >> 5;                 // 0..7
    const int row  = blockIdx.x * 8 + w;       // 0..2047

    float acc = 0.0f;
    for (int k0 = 0; k0 < HID; k0 += 32) {
        __syncthreads();
#pragma unroll
        for (int p = 0; p < 4; ++p) {
            int idx = tid + p * 256;           // 0..1023
            ws[idx >> 5][idx & 31] = W3[k0 * DDIM + idx];
        }
        __syncthreads();
        float hv = g_h2[row * HID + k0 + lane];
#pragma unroll
        for (int j = 0; j < 32; ++j)
            acc = fmaf(__shfl_sync(0xffffffffu, hv, j), ws[j][lane], acc);
    }
    float kv = acc + b3[lane];

    int   ti = row * DDIM + lane;
    float th = g_theta[ti];
    float arg;
    if (stage == 0) {
        g_ksum[ti] = kv;
        arg = th + 0.5f * dt * kv;
    } else if (stage == 1) {
        g_ksum[ti] += 2.0f * kv;
        arg = th + 0.5f * dt * kv;
    } else if (stage == 2) {
        g_ksum[ti] += 2.0f * kv;
        arg = th + dt * kv;
    } else {
        float ks  = g_ksum[ti] + kv;
        float nth = th + (dt / 6.0f) * ks;
        g_theta[ti] = nth;
        arg = nth;
        if (final_out) final_out[ti] = nth;
    }
    g_xbuf[row * INPAD + lane] = arg;
    if (lane == 0) g_xbuf[row * INPAD + DDIM] = t_next;
}

// ---------------- host launcher ----------------
extern "C" void kernel_launch(void* const* d_in, const int* in_sizes, int n_in,
                              void* d_out, int out_size) {
    const float* theta0  = (const float*)d_in[0];
    const float* context = (const float*)d_in[1];
    const float* W1      = (const float*)d_in[2];
    const float* b1      = (const float*)d_in[3];
    const float* W2      = (const float*)d_in[4];
    const float* b2      = (const float*)d_in[5];
    const float* W3      = (const float*)d_in[6];
    const float* b3      = (const float*)d_in[7];
    float* out = (float*)d_out;

    float *xbuf, *h1, *h2, *w1p;
    cudaGetSymbolAddress((void**)&xbuf, g_xbuf);
    cudaGetSymbolAddress((void**)&h1,   g_h1);
    cudaGetSymbolAddress((void**)&h2,   g_h2);
    cudaGetSymbolAddress((void**)&w1p,  g_W1p);

    init_pad_w1<<<(INPAD * 1024 + 255) / 256, 256>>>(W1);
    init_x<<<BATCH, 192>>>(theta0, context);

    const float dt = 1.0f / NSTEPS;
    dim3 ggrid(HID / BN, BATCH / BM);   // (8, 16)

    for (int i = 0; i < NSTEPS; ++i) {
        float t0 = (float)i * dt;
        for (int s = 0; s < 4; ++s) {
            glu_gemm<<<ggrid, 256>>>(xbuf, INPAD, INPAD, w1p, b1, h1);
            glu_gemm<<<ggrid, 256>>>(h1, HID, HID, W2, b2, h2);
            float t_next = (s <= 1) ? (t0 + 0.5f * dt) : (t0 + dt);
            bool last = (i == NSTEPS - 1) && (s == 3);
            k3_update<<<BATCH / 8, 256>>>(W3, b3, s, t_next, dt,
                                          last ? out : nullptr);
        }
    }
}

// round 3
// speedup vs baseline: 1.6113x; 1.6113x over previous
#include <cuda_runtime.h>
#include <cuda_bf16.h>
#include <math.h>
#include <stdint.h>

// ---------------- problem constants ----------------
#define BATCH  2048
#define DDIM   32
#define CDIM   128
#define HID    512
#define INRAW  161
#define KP1    192     // padded K for layer 1
#define KP2    512     // K for layer 2
#define NSTEPS 16

// ---------------- device scratch (allocation-free) ----------------
__device__ __align__(16) __nv_bfloat16 g_x_hi [BATCH * KP1];
__device__ __align__(16) __nv_bfloat16 g_x_lo [BATCH * KP1];
__device__ __align__(16) __nv_bfloat16 g_h1_hi[BATCH * HID];
__device__ __align__(16) __nv_bfloat16 g_h1_lo[BATCH * HID];
__device__ __align__(16) float         g_h2   [BATCH * HID];
__device__ __align__(16) float         g_theta[BATCH * DDIM];
__device__ __align__(16) float         g_ksum [BATCH * DDIM];
// transposed + bf16-split weights: Bt[n][k] = W[k][n]
__device__ __align__(16) __nv_bfloat16 g_B1_hi[1024 * KP1];
__device__ __align__(16) __nv_bfloat16 g_B1_lo[1024 * KP1];
__device__ __align__(16) __nv_bfloat16 g_B2_hi[1024 * KP2];
__device__ __align__(16) __nv_bfloat16 g_B2_lo[1024 * KP2];

// ---------------- PTX helpers (compute_100-safe: sm_80-era ops) ----------------
__device__ __forceinline__ uint32_t smem_u32(const void* p) {
    uint32_t a;
    asm("{ .reg .u64 t; cvta.to.shared.u64 t, %1; cvt.u32.u64 %0, t; }"
        : "=r"(a) : "l"(p));
    return a;
}
__device__ __forceinline__ void cpasync16(uint32_t saddr, const void* g) {
    asm volatile("cp.async.cg.shared.global [%0], [%1], 16;"
                 :: "r"(saddr), "l"(g) : "memory");
}
#define CP_COMMIT() asm volatile("cp.async.commit_group;" ::: "memory")
#define CP_WAIT0()  asm volatile("cp.async.wait_group 0;" ::: "memory")

__device__ __forceinline__ void ldsm4(uint32_t* r, uint32_t addr) {
    asm volatile("ldmatrix.sync.aligned.m8n8.x4.shared.b16 {%0,%1,%2,%3}, [%4];"
                 : "=r"(r[0]), "=r"(r[1]), "=r"(r[2]), "=r"(r[3]) : "r"(addr));
}
__device__ __forceinline__ void mma16816(float* c, const uint32_t* a, const uint32_t* b) {
    asm volatile("mma.sync.aligned.m16n8k16.row.col.f32.bf16.bf16.f32 "
                 "{%0,%1,%2,%3}, {%4,%5,%6,%7}, {%8,%9}, {%0,%1,%2,%3};"
                 : "+f"(c[0]), "+f"(c[1]), "+f"(c[2]), "+f"(c[3])
                 : "r"(a[0]), "r"(a[1]), "r"(a[2]), "r"(a[3]),
                   "r"(b[0]), "r"(b[1]));
}

__device__ __forceinline__ void bf16split(float v, __nv_bfloat16& h, __nv_bfloat16& l) {
    h = __float2bfloat16(v);
    l = __float2bfloat16(v - __bfloat162float(h));
}

// ---------------- init kernels ----------------
__global__ void init_wt(const float* __restrict__ W, int Kraw, int Kpad,
                        __nv_bfloat16* __restrict__ dh, __nv_bfloat16* __restrict__ dl) {
    int idx = blockIdx.x * blockDim.x + threadIdx.x;
    if (idx >= 1024 * Kpad) return;
    int n = idx / Kpad, k = idx - n * Kpad;
    float v = (k < Kraw) ? W[(size_t)k * 1024 + n] : 0.0f;
    __nv_bfloat16 h, l; bf16split(v, h, l);
    dh[idx] = h; dl[idx] = l;
}

__global__ void init_x(const float* __restrict__ theta0,
                       const float* __restrict__ context) {
    int r = blockIdx.x, t = threadIdx.x;   // blockDim = 192
    float v;
    if (t < DDIM) {
        v = theta0[r * DDIM + t];
        g_theta[r * DDIM + t] = v;
    } else if (t == DDIM) {
        v = 0.0f;                                   // t = 0
    } else if (t < INRAW) {
        v = context[r * CDIM + (t - DDIM - 1)];
    } else {
        v = 0.0f;                                   // K pad
    }
    __nv_bfloat16 h, l; bf16split(v, h, l);
    g_x_hi[(size_t)r * KP1 + t] = h;
    g_x_lo[(size_t)r * KP1 + t] = l;
}

// ---------------- fused bf16 mma.sync GEMM + GLU ----------------
// out[m,n] = ((A@W)[:,n]+bias[n]) * sigmoid((A@W)[:,n+512]+bias[n+512])
// A (bf16 hi/lo) [2048 x Kpad] row-major; Bt (bf16 hi/lo) [1024 x Kpad] row-major
// (= B col-major as mma.row.col wants).
// CTA: M=128, cols [bn,bn+64) a-half and [bn+512, ...) b-half; BK=64; 8 warps 4x2.
#define ROWE  72                        // smem row stride in bf16 elems (pad vs banks)
#define TILE_B (128 * ROWE * 2)         // 18432 B per tile
#define OFF_AH 0
#define OFF_AL (TILE_B)
#define OFF_BH (2 * TILE_B)
#define OFF_BL (3 * TILE_B)
#define STAGE_B (4 * TILE_B)            // 73728
#define GLU_SMEM (2 * STAGE_B)          // 147456

__global__ __launch_bounds__(256)
void glu_mma(const __nv_bfloat16* __restrict__ Ah, const __nv_bfloat16* __restrict__ Al,
             int lda, int nch,
             const __nv_bfloat16* __restrict__ Bh, const __nv_bfloat16* __restrict__ Bl,
             int ldb, const float* __restrict__ bias, int out_mode,
             __nv_bfloat16* __restrict__ outh, __nv_bfloat16* __restrict__ outl,
             float* __restrict__ outf) {
    extern __shared__ char smem[];
    const uint32_t sb = smem_u32(smem);
    const int tid  = threadIdx.x;
    const int lane = tid & 31, wid = tid >> 5;
    const int wm = wid & 3;          // warp row (32 rows each)
    const int wn = wid >> 2;         // warp col (32 cols per half each)
    const int bm = blockIdx.y * 128, bn = blockIdx.x * 64;

    float acc[2][8][4];              // [mi][h*4+nt][4]
#pragma unroll
    for (int i = 0; i < 2; ++i)
#pragma unroll
        for (int j = 0; j < 8; ++j)
#pragma unroll
            for (int q = 0; q < 4; ++q) acc[i][j][q] = 0.0f;

    // chunk loader: 4 x 16B per thread per tile, 4 tiles
    auto issue = [&](int c) {
        const int kc = c * 64;
        const uint32_t st = sb + (uint32_t)((c & 1) * STAGE_B);
#pragma unroll
        for (int p = 0; p < 4; ++p) {
            int slot = p * 256 + tid;
            int row = slot >> 3, cc = slot & 7;
            uint32_t so = (uint32_t)(row * ROWE + cc * 8) * 2;
            const __nv_bfloat16* gah = Ah + (size_t)(bm + row) * lda + kc + cc * 8;
            const __nv_bfloat16* gal = Al + (size_t)(bm + row) * lda + kc + cc * 8;
            int brow = (row < 64) ? (bn + row) : (448 + bn + row);  // 512+bn+(row-64)
            const __nv_bfloat16* gbh = Bh + (size_t)brow * ldb + kc + cc * 8;
            const __nv_bfloat16* gbl = Bl + (size_t)brow * ldb + kc + cc * 8;
            cpasync16(st + OFF_AH + so, gah);
            cpasync16(st + OFF_AL + so, gal);
            cpasync16(st + OFF_BH + so, gbh);
            cpasync16(st + OFF_BL + so, gbl);
        }
        CP_COMMIT();
    };

    // ldmatrix lane offsets (bytes, within a tile)
    const uint32_t a_off = (uint32_t)((wm * 32 + (lane & 15)) * ROWE
                                      + ((lane >> 4) << 3)) * 2;
    const uint32_t b_off = (uint32_t)((wn * 32 + ((lane >> 4) << 3) + (lane & 7)) * ROWE
                                      + (((lane >> 3) & 1) << 3)) * 2;

    issue(0);

    for (int c = 0; c < nch; ++c) {
        CP_WAIT0();
        __syncthreads();
        if (c + 1 < nch) issue(c + 1);

        const uint32_t st = sb + (uint32_t)((c & 1) * STAGE_B);
#pragma unroll
        for (int kk = 0; kk < 4; ++kk) {
            const uint32_t kb = (uint32_t)(kk * 16) * 2;
            uint32_t af[2][2][4];    // [hi/lo][mi][4]
#pragma unroll
            for (int mi = 0; mi < 2; ++mi) {
                uint32_t o = a_off + (uint32_t)(mi * 16 * ROWE) * 2 + kb;
                ldsm4(af[0][mi], st + OFF_AH + o);
                ldsm4(af[1][mi], st + OFF_AL + o);
            }
#pragma unroll
            for (int h = 0; h < 2; ++h) {
                uint32_t bf[2][2][4];  // [hi/lo][p][4] -> tiles (2p, 2p+1)
#pragma unroll
                for (int p = 0; p < 2; ++p) {
                    uint32_t o = b_off + (uint32_t)((h * 64 + p * 16) * ROWE) * 2 + kb;
                    ldsm4(bf[0][p], st + OFF_BH + o);
                    ldsm4(bf[1][p], st + OFF_BL + o);
                }
#pragma unroll
                for (int mi = 0; mi < 2; ++mi)
#pragma unroll
                    for (int p = 0; p < 2; ++p)
#pragma unroll
                        for (int q = 0; q < 2; ++q) {
                            float* cc2 = acc[mi][h * 4 + p * 2 + q];
                            mma16816(cc2, af[0][mi], &bf[0][p][q * 2]);  // hi*hi
                            mma16816(cc2, af[0][mi], &bf[1][p][q * 2]);  // hi*lo
                            mma16816(cc2, af[1][mi], &bf[0][p][q * 2]);  // lo*hi
                        }
            }
        }
        __syncthreads();
    }

    // ---------------- GLU epilogue ----------------
    const int r0 = bm + wm * 32 + (lane >> 2);
    const int cb = wn * 32 + (lane & 3) * 2;
#pragma unroll
    for (int mi = 0; mi < 2; ++mi)
#pragma unroll
        for (int nt = 0; nt < 4; ++nt) {
            int gcol = bn + cb + nt * 8;
            float bia0 = bias[gcol],       bia1 = bias[gcol + 1];
            float bib0 = bias[512 + gcol], bib1 = bias[512 + gcol + 1];
            const float* ca = acc[mi][nt];
            const float* cbv = acc[mi][4 + nt];
            float g00 = (ca[0] + bia0) / (1.0f + __expf(-(cbv[0] + bib0)));
            float g01 = (ca[1] + bia1) / (1.0f + __expf(-(cbv[1] + bib1)));
            float g10 = (ca[2] + bia0) / (1.0f + __expf(-(cbv[2] + bib0)));
            float g11 = (ca[3] + bia1) / (1.0f + __expf(-(cbv[3] + bib1)));
            int ra = r0 + mi * 16;
            size_t o0 = (size_t)ra * HID + gcol;
            size_t o1 = (size_t)(ra + 8) * HID + gcol;
            if (out_mode == 0) {
                __nv_bfloat16 h0, l0, h1, l1;
                bf16split(g00, h0, l0); bf16split(g01, h1, l1);
                *(__nv_bfloat162*)(outh + o0) = __nv_bfloat162(h0, h1);
                *(__nv_bfloat162*)(outl + o0) = __nv_bfloat162(l0, l1);
                bf16split(g10, h0, l0); bf16split(g11, h1, l1);
                *(__nv_bfloat162*)(outh + o1) = __nv_bfloat162(h0, h1);
                *(__nv_bfloat162*)(outl + o1) = __nv_bfloat162(l0, l1);
            } else {
                *(float2*)(outf + o0) = make_float2(g00, g01);
                *(float2*)(outf + o1) = make_float2(g10, g11);
            }
        }
}

// ---------------- layer 3 + RK4 stage update (fp32) ----------------
__global__ __launch_bounds__(256)
void k3_update(const float* __restrict__ W3, const float* __restrict__ b3,
               int stage, float t_next, float dt, float* __restrict__ final_out) {
    extern __shared__ float ws[];   // [512][32]
    const int tid = threadIdx.x;
    for (int i = tid; i < HID * DDIM; i += 256) ws[i] = W3[i];
    __syncthreads();

    const int r  = blockIdx.x * 32 + (tid >> 3);
    const int c0 = (tid & 7) * 4;
    const float* h2r = g_h2 + (size_t)r * HID;

    float a0 = 0.f, a1 = 0.f, a2 = 0.f, a3 = 0.f;
#pragma unroll 8
    for (int k = 0; k < HID; ++k) {
        float hv = h2r[k];
        float4 w = *(const float4*)&ws[k * DDIM + c0];
        a0 = fmaf(hv, w.x, a0); a1 = fmaf(hv, w.y, a1);
        a2 = fmaf(hv, w.z, a2); a3 = fmaf(hv, w.w, a3);
    }
    float kv[4] = { a0 + b3[c0], a1 + b3[c0 + 1], a2 + b3[c0 + 2], a3 + b3[c0 + 3] };

#pragma unroll
    for (int j = 0; j < 4; ++j) {
        int c = c0 + j;
        int ti = r * DDIM + c;
        float th = g_theta[ti];
        float arg;
        if (stage == 0)      { g_ksum[ti] = kv[j];          arg = th + 0.5f * dt * kv[j]; }
        else if (stage == 1) { g_ksum[ti] += 2.0f * kv[j];  arg = th + 0.5f * dt * kv[j]; }
        else if (stage == 2) { g_ksum[ti] += 2.0f * kv[j];  arg = th + dt * kv[j]; }
        else {
            float ks  = g_ksum[ti] + kv[j];
            float nth = th + (dt / 6.0f) * ks;
            g_theta[ti] = nth;
            arg = nth;
            if (final_out) final_out[ti] = nth;
        }
        __nv_bfloat16 h, l; bf16split(arg, h, l);
        g_x_hi[(size_t)r * KP1 + c] = h;
        g_x_lo[(size_t)r * KP1 + c] = l;
    }
    if ((tid & 7) == 0) {
        __nv_bfloat16 h, l; bf16split(t_next, h, l);
        g_x_hi[(size_t)r * KP1 + DDIM] = h;
        g_x_lo[(size_t)r * KP1 + DDIM] = l;
    }
}

// ---------------- host launcher ----------------
extern "C" void kernel_launch(void* const* d_in, const int* in_sizes, int n_in,
                              void* d_out, int out_size) {
    const float* theta0  = (const float*)d_in[0];
    const float* context = (const float*)d_in[1];
    const float* W1      = (const float*)d_in[2];
    const float* b1      = (const float*)d_in[3];
    const float* W2      = (const float*)d_in[4];
    const float* b2      = (const float*)d_in[5];
    const float* W3      = (const float*)d_in[6];
    const float* b3      = (const float*)d_in[7];
    float* out = (float*)d_out;

    __nv_bfloat16 *xh, *xl, *h1h, *h1l, *b1h, *b1l, *b2h, *b2l;
    float* h2;
    cudaGetSymbolAddress((void**)&xh,  g_x_hi);
    cudaGetSymbolAddress((void**)&xl,  g_x_lo);
    cudaGetSymbolAddress((void**)&h1h, g_h1_hi);
    cudaGetSymbolAddress((void**)&h1l, g_h1_lo);
    cudaGetSymbolAddress((void**)&h2,  g_h2);
    cudaGetSymbolAddress((void**)&b1h, g_B1_hi);
    cudaGetSymbolAddress((void**)&b1l, g_B1_lo);
    cudaGetSymbolAddress((void**)&b2h, g_B2_hi);
    cudaGetSymbolAddress((void**)&b2l, g_B2_lo);

    cudaFuncSetAttribute(glu_mma, cudaFuncAttributeMaxDynamicSharedMemorySize, GLU_SMEM);
    cudaFuncSetAttribute(k3_update, cudaFuncAttributeMaxDynamicSharedMemorySize,
                         HID * DDIM * (int)sizeof(float));

    init_wt<<<(1024 * KP1 + 255) / 256, 256>>>(W1, INRAW, KP1, b1h, b1l);
    init_wt<<<(1024 * KP2 + 255) / 256, 256>>>(W2, KP2,   KP2, b2h, b2l);
    init_x<<<BATCH, KP1>>>(theta0, context);

    const float dt = 1.0f / NSTEPS;
    dim3 ggrid(HID / 64, BATCH / 128);   // (8, 16)

    for (int i = 0; i < NSTEPS; ++i) {
        float t0 = (float)i * dt;
        for (int s = 0; s < 4; ++s) {
            glu_mma<<<ggrid, 256, GLU_SMEM>>>(xh, xl, KP1, KP1 / 64, b1h, b1l, KP1,
                                              b1, 0, h1h, h1l, nullptr);
            glu_mma<<<ggrid, 256, GLU_SMEM>>>(h1h, h1l, KP2, KP2 / 64, b2h, b2l, KP2,
                                              b2, 1, nullptr, nullptr, h2);
            float t_next = (s <= 1) ? (t0 + 0.5f * dt) : (t0 + dt);
            bool last = (i == NSTEPS - 1) && (s == 3);
            k3_update<<<BATCH / 32, 256, HID * DDIM * (int)sizeof(float)>>>(
                W3, b3, s, t_next, dt, last ? out : nullptr);
        }
    }
}

// round 4
// speedup vs baseline: 2.2140x; 1.3741x over previous
#include <cuda_runtime.h>
#include <cuda_bf16.h>
#include <math.h>
#include <stdint.h>

// ---------------- problem constants ----------------
#define BATCH  2048
#define DDIM   32
#define CDIM   128
#define HID    512
#define INRAW  161
#define KP1    192     // padded K for layer 1
#define KP2    512     // K for layer 2
#define NSTEPS 16

// ---------------- device scratch (allocation-free) ----------------
__device__ __align__(16) __nv_bfloat16 g_x_hi [BATCH * KP1];
__device__ __align__(16) __nv_bfloat16 g_x_lo [BATCH * KP1];
__device__ __align__(16) __nv_bfloat16 g_h1_hi[BATCH * HID];
__device__ __align__(16) __nv_bfloat16 g_h1_lo[BATCH * HID];
__device__ __align__(16) __nv_bfloat16 g_h2_hi[BATCH * HID];
__device__ __align__(16) __nv_bfloat16 g_h2_lo[BATCH * HID];
__device__ __align__(16) float         g_theta[BATCH * DDIM];
__device__ __align__(16) float         g_ksum [BATCH * DDIM];
// transposed + bf16-split weights: Bt[n][k] = W[k][n]
__device__ __align__(16) __nv_bfloat16 g_B1_hi[1024 * KP1];
__device__ __align__(16) __nv_bfloat16 g_B1_lo[1024 * KP1];
__device__ __align__(16) __nv_bfloat16 g_B2_hi[1024 * KP2];
__device__ __align__(16) __nv_bfloat16 g_B2_lo[1024 * KP2];
// W3 transposed: W3t[n][k] = W3[k][n], n<32, k<512
__device__ __align__(16) __nv_bfloat16 g_W3t_hi[DDIM * HID];
__device__ __align__(16) __nv_bfloat16 g_W3t_lo[DDIM * HID];

// ---------------- PTX helpers (compute_100-safe: sm_80-era ops) ----------------
__device__ __forceinline__ uint32_t smem_u32(const void* p) {
    uint32_t a;
    asm("{ .reg .u64 t; cvta.to.shared.u64 t, %1; cvt.u32.u64 %0, t; }"
        : "=r"(a) : "l"(p));
    return a;
}
__device__ __forceinline__ void cpasync16(uint32_t saddr, const void* g) {
    asm volatile("cp.async.cg.shared.global [%0], [%1], 16;"
                 :: "r"(saddr), "l"(g) : "memory");
}
#define CP_COMMIT() asm volatile("cp.async.commit_group;" ::: "memory")
#define CP_WAIT0()  asm volatile("cp.async.wait_group 0;" ::: "memory")
#define CP_WAIT1()  asm volatile("cp.async.wait_group 1;" ::: "memory")

__device__ __forceinline__ void ldsm4(uint32_t* r, uint32_t addr) {
    asm volatile("ldmatrix.sync.aligned.m8n8.x4.shared.b16 {%0,%1,%2,%3}, [%4];"
                 : "=r"(r[0]), "=r"(r[1]), "=r"(r[2]), "=r"(r[3]) : "r"(addr));
}
__device__ __forceinline__ void mma16816(float* c, const uint32_t* a, const uint32_t* b) {
    asm volatile("mma.sync.aligned.m16n8k16.row.col.f32.bf16.bf16.f32 "
                 "{%0,%1,%2,%3}, {%4,%5,%6,%7}, {%8,%9}, {%0,%1,%2,%3};"
                 : "+f"(c[0]), "+f"(c[1]), "+f"(c[2]), "+f"(c[3])
                 : "r"(a[0]), "r"(a[1]), "r"(a[2]), "r"(a[3]),
                   "r"(b[0]), "r"(b[1]));
}

__device__ __forceinline__ void bf16split(float v, __nv_bfloat16& h, __nv_bfloat16& l) {
    h = __float2bfloat16(v);
    l = __float2bfloat16(v - __bfloat162float(h));
}

// ---------------- init kernels ----------------
__global__ void init_wt(const float* __restrict__ W, int Kraw, int Kpad,
                        __nv_bfloat16* __restrict__ dh, __nv_bfloat16* __restrict__ dl) {
    int idx = blockIdx.x * blockDim.x + threadIdx.x;
    if (idx >= 1024 * Kpad) return;
    int n = idx / Kpad, k = idx - n * Kpad;
    float v = (k < Kraw) ? W[(size_t)k * 1024 + n] : 0.0f;
    __nv_bfloat16 h, l; bf16split(v, h, l);
    dh[idx] = h; dl[idx] = l;
}

__global__ void init_w3t(const float* __restrict__ W3) {
    int idx = blockIdx.x * blockDim.x + threadIdx.x;   // 0..16383
    if (idx >= DDIM * HID) return;
    int n = idx >> 9, k = idx & 511;
    __nv_bfloat16 h, l; bf16split(W3[(size_t)k * DDIM + n], h, l);
    g_W3t_hi[idx] = h; g_W3t_lo[idx] = l;
}

__global__ void init_x(const float* __restrict__ theta0,
                       const float* __restrict__ context) {
    int r = blockIdx.x, t = threadIdx.x;   // blockDim = 192
    float v;
    if (t < DDIM) {
        v = theta0[r * DDIM + t];
        g_theta[r * DDIM + t] = v;
    } else if (t == DDIM) {
        v = 0.0f;                                   // t = 0
    } else if (t < INRAW) {
        v = context[r * CDIM + (t - DDIM - 1)];
    } else {
        v = 0.0f;                                   // K pad
    }
    __nv_bfloat16 h, l; bf16split(v, h, l);
    g_x_hi[(size_t)r * KP1 + t] = h;
    g_x_lo[(size_t)r * KP1 + t] = l;
}

// ---------------- fused bf16 mma.sync GEMM + GLU ----------------
// out = GLU(A @ W + bias); 3-term bf16 split, fp32 accumulate.
// CTA: M=128, cols [bn,bn+64) per half; BK=64; 8 warps 4x2; 3-stage cp.async.
#define ROWE  72                        // smem row stride in bf16 elems
#define TILE_B (128 * ROWE * 2)         // 18432 B per matrix
#define OFF_AH 0
#define OFF_AL (TILE_B)
#define OFF_BH (2 * TILE_B)
#define OFF_BL (3 * TILE_B)
#define STAGE_B (4 * TILE_B)            // 73728
#define GLU_SMEM (3 * STAGE_B)          // 221184

__global__ __launch_bounds__(256)
void glu_mma(const __nv_bfloat16* __restrict__ Ah, const __nv_bfloat16* __restrict__ Al,
             int lda, int nch,
             const __nv_bfloat16* __restrict__ Bh, const __nv_bfloat16* __restrict__ Bl,
             int ldb, const float* __restrict__ bias,
             __nv_bfloat16* __restrict__ outh, __nv_bfloat16* __restrict__ outl) {
    extern __shared__ char smem[];
    const uint32_t sb = smem_u32(smem);
    const int tid  = threadIdx.x;
    const int lane = tid & 31, wid = tid >> 5;
    const int wm = wid & 3;          // warp row (32 rows each)
    const int wn = wid >> 2;         // warp col (32 cols per half each)
    const int bm = blockIdx.y * 128, bn = blockIdx.x * 64;

    float acc[2][8][4];
#pragma unroll
    for (int i = 0; i < 2; ++i)
#pragma unroll
        for (int j = 0; j < 8; ++j)
#pragma unroll
            for (int q = 0; q < 4; ++q) acc[i][j][q] = 0.0f;

    auto issue = [&](int c) {
        const int kc = c * 64;
        const uint32_t st = sb + (uint32_t)((c % 3) * STAGE_B);
#pragma unroll
        for (int p = 0; p < 4; ++p) {
            int slot = p * 256 + tid;
            int row = slot >> 3, cc = slot & 7;
            uint32_t so = (uint32_t)(row * ROWE + cc * 8) * 2;
            const __nv_bfloat16* gah = Ah + (size_t)(bm + row) * lda + kc + cc * 8;
            const __nv_bfloat16* gal = Al + (size_t)(bm + row) * lda + kc + cc * 8;
            int brow = (row < 64) ? (bn + row) : (448 + bn + row);
            const __nv_bfloat16* gbh = Bh + (size_t)brow * ldb + kc + cc * 8;
            const __nv_bfloat16* gbl = Bl + (size_t)brow * ldb + kc + cc * 8;
            cpasync16(st + OFF_AH + so, gah);
            cpasync16(st + OFF_AL + so, gal);
            cpasync16(st + OFF_BH + so, gbh);
            cpasync16(st + OFF_BL + so, gbl);
        }
        CP_COMMIT();
    };

    const uint32_t a_off = (uint32_t)((wm * 32 + (lane & 15)) * ROWE
                                      + ((lane >> 4) << 3)) * 2;
    const uint32_t b_off = (uint32_t)((wn * 32 + ((lane >> 4) << 3) + (lane & 7)) * ROWE
                                      + (((lane >> 3) & 1) << 3)) * 2;

    issue(0);
    if (nch > 1) issue(1);

    for (int c = 0; c < nch; ++c) {
        if (c + 1 < nch) CP_WAIT1(); else CP_WAIT0();
        __syncthreads();
        if (c + 2 < nch) issue(c + 2);

        const uint32_t st = sb + (uint32_t)((c % 3) * STAGE_B);
#pragma unroll
        for (int kk = 0; kk < 4; ++kk) {
            const uint32_t kb = (uint32_t)(kk * 16) * 2;
            uint32_t af[2][2][4];
#pragma unroll
            for (int mi = 0; mi < 2; ++mi) {
                uint32_t o = a_off + (uint32_t)(mi * 16 * ROWE) * 2 + kb;
                ldsm4(af[0][mi], st + OFF_AH + o);
                ldsm4(af[1][mi], st + OFF_AL + o);
            }
#pragma unroll
            for (int h = 0; h < 2; ++h) {
                uint32_t bf[2][2][4];
#pragma unroll
                for (int p = 0; p < 2; ++p) {
                    uint32_t o = b_off + (uint32_t)((h * 64 + p * 16) * ROWE) * 2 + kb;
                    ldsm4(bf[0][p], st + OFF_BH + o);
                    ldsm4(bf[1][p], st + OFF_BL + o);
                }
#pragma unroll
                for (int mi = 0; mi < 2; ++mi)
#pragma unroll
                    for (int p = 0; p < 2; ++p)
#pragma unroll
                        for (int q = 0; q < 2; ++q) {
                            float* cc2 = acc[mi][h * 4 + p * 2 + q];
                            mma16816(cc2, af[0][mi], &bf[0][p][q * 2]);  // hi*hi
                            mma16816(cc2, af[0][mi], &bf[1][p][q * 2]);  // hi*lo
                            mma16816(cc2, af[1][mi], &bf[0][p][q * 2]);  // lo*hi
                        }
            }
        }
    }

    // ---------------- GLU epilogue (bf16 hi/lo out) ----------------
    const int r0 = bm + wm * 32 + (lane >> 2);
    const int cb = wn * 32 + (lane & 3) * 2;
#pragma unroll
    for (int mi = 0; mi < 2; ++mi)
#pragma unroll
        for (int nt = 0; nt < 4; ++nt) {
            int gcol = bn + cb + nt * 8;
            float bia0 = bias[gcol],       bia1 = bias[gcol + 1];
            float bib0 = bias[512 + gcol], bib1 = bias[512 + gcol + 1];
            const float* ca = acc[mi][nt];
            const float* cbv = acc[mi][4 + nt];
            float g00 = (ca[0] + bia0) / (1.0f + __expf(-(cbv[0] + bib0)));
            float g01 = (ca[1] + bia1) / (1.0f + __expf(-(cbv[1] + bib1)));
            float g10 = (ca[2] + bia0) / (1.0f + __expf(-(cbv[2] + bib0)));
            float g11 = (ca[3] + bia1) / (1.0f + __expf(-(cbv[3] + bib1)));
            int ra = r0 + mi * 16;
            size_t o0 = (size_t)ra * HID + gcol;
            size_t o1 = (size_t)(ra + 8) * HID + gcol;
            __nv_bfloat16 h0, l0, h1, l1;
            bf16split(g00, h0, l0); bf16split(g01, h1, l1);
            *(__nv_bfloat162*)(outh + o0) = __nv_bfloat162(h0, h1);
            *(__nv_bfloat162*)(outl + o0) = __nv_bfloat162(l0, l1);
            bf16split(g10, h0, l0); bf16split(g11, h1, l1);
            *(__nv_bfloat162*)(outh + o1) = __nv_bfloat162(h0, h1);
            *(__nv_bfloat162*)(outl + o1) = __nv_bfloat162(l0, l1);
        }
}

// ---------------- layer 3 (mma) + fused RK4 stage update ----------------
// grid 32 CTAs x 128 thr (4 warps); CTA = 64 batch rows x all 32 out dims.
// W3t (hi/lo) kept in smem for the whole kernel; A = h2 hi/lo, 3-stage pipeline.
#define K3_WROW 520                      // W3t smem row stride (elems)
#define K3_OFF_WH 0
#define K3_OFF_WL (32 * K3_WROW * 2)     // 33280
#define K3_AROW 72
#define K3_OFF_A (2 * 32 * K3_WROW * 2)  // 66560
#define K3_APREC (64 * K3_AROW * 2)      // 9216 per precision
#define K3_ASTG (2 * K3_APREC)           // 18432 per stage
#define K3_SMEM (K3_OFF_A + 3 * K3_ASTG) // 121856

__global__ __launch_bounds__(128)
void k3_mma(const float* __restrict__ b3, int stage, float t_next, float dt,
            float* __restrict__ final_out) {
    extern __shared__ char smem[];
    const uint32_t sb = smem_u32(smem);
    const int tid = threadIdx.x, lane = tid & 31, w = tid >> 5;
    const int bm = blockIdx.x * 64;

    auto issueA = [&](int c) {
        const uint32_t st = sb + K3_OFF_A + (uint32_t)((c % 3) * K3_ASTG);
        const int kc = c * 64;
#pragma unroll
        for (int p = 0; p < 8; ++p) {
            int slot = p * 128 + tid;        // 0..1023
            int prec = slot >> 9;
            int s2 = slot & 511;
            int row = s2 >> 3, cc = s2 & 7;
            uint32_t so = (uint32_t)(prec * K3_APREC + (row * K3_AROW + cc * 8) * 2);
            const __nv_bfloat16* g = (prec ? g_h2_lo : g_h2_hi)
                                     + (size_t)(bm + row) * HID + kc + cc * 8;
            cpasync16(st + so, g);
        }
        CP_COMMIT();
    };

    // W3t one-time loads, folded into group 0
#pragma unroll
    for (int p = 0; p < 32; ++p) {
        int slot = p * 128 + tid;            // 0..4095
        int prec = slot >> 11;
        int s2 = slot & 2047;
        int row = s2 >> 6, cc = s2 & 63;     // 16B units along k
        uint32_t so = (uint32_t)((prec ? K3_OFF_WL : K3_OFF_WH) + row * (K3_WROW * 2) + cc * 16);
        const __nv_bfloat16* g = (prec ? g_W3t_lo : g_W3t_hi) + (size_t)row * HID + cc * 8;
        cpasync16(sb + so, g);
    }
    issueA(0);
    issueA(1);

    float acc[4][4];
#pragma unroll
    for (int i = 0; i < 4; ++i)
#pragma unroll
        for (int j = 0; j < 4; ++j) acc[i][j] = 0.0f;

    const uint32_t a_base = (uint32_t)((w * 16 + (lane & 15)) * K3_AROW
                                       + ((lane >> 4) << 3)) * 2;

    for (int c = 0; c < 8; ++c) {
        if (c + 1 < 8) CP_WAIT1(); else CP_WAIT0();
        __syncthreads();
        if (c + 2 < 8) issueA(c + 2);

        const uint32_t st = sb + K3_OFF_A + (uint32_t)((c % 3) * K3_ASTG);
        const int kc = c * 64;
#pragma unroll
        for (int kk = 0; kk < 4; ++kk) {
            const uint32_t kb = (uint32_t)(kk * 16) * 2;
            uint32_t ah[4], al[4];
            ldsm4(ah, st + a_base + kb);
            ldsm4(al, st + K3_APREC + a_base + kb);
#pragma unroll
            for (int p = 0; p < 2; ++p) {
                uint32_t boff = (uint32_t)((p * 16 + ((lane >> 4) << 3) + (lane & 7)) * K3_WROW
                                           + kc + kk * 16 + (((lane >> 3) & 1) << 3)) * 2;
                uint32_t bh[4], bl[4];
                ldsm4(bh, sb + K3_OFF_WH + boff);
                ldsm4(bl, sb + K3_OFF_WL + boff);
#pragma unroll
                for (int q = 0; q < 2; ++q) {
                    float* cc2 = acc[p * 2 + q];
                    mma16816(cc2, ah, &bh[q * 2]);
                    mma16816(cc2, ah, &bl[q * 2]);
                    mma16816(cc2, al, &bh[q * 2]);
                }
            }
        }
    }

    // ---------------- fused RK4 epilogue ----------------
    const float dt6 = dt / 6.0f;
#pragma unroll
    for (int nt = 0; nt < 4; ++nt) {
        int col = (nt >> 1) * 16 + (nt & 1) * 8 + (lane & 3) * 2;
#pragma unroll
        for (int half = 0; half < 2; ++half) {
            int r = bm + w * 16 + (lane >> 2) + half * 8;
#pragma unroll
            for (int j = 0; j < 2; ++j) {
                int c = col + j;
                float kv = acc[nt][half * 2 + j] + b3[c];
                int ti = r * DDIM + c;
                float th = g_theta[ti];
                float arg;
                if (stage == 0)      { g_ksum[ti] = kv;         arg = th + 0.5f * dt * kv; }
                else if (stage == 1) { g_ksum[ti] += 2.0f * kv; arg = th + 0.5f * dt * kv; }
                else if (stage == 2) { g_ksum[ti] += 2.0f * kv; arg = th + dt * kv; }
                else {
                    float nth = th + dt6 * (g_ksum[ti] + kv);
                    g_theta[ti] = nth;
                    arg = nth;
                    if (final_out) final_out[ti] = nth;
                }
                __nv_bfloat16 h, l; bf16split(arg, h, l);
                g_x_hi[(size_t)r * KP1 + c] = h;
                g_x_lo[(size_t)r * KP1 + c] = l;
            }
        }
    }
    if ((lane & 3) == 0) {
        __nv_bfloat16 h, l; bf16split(t_next, h, l);
        int r = bm + w * 16 + (lane >> 2);
        g_x_hi[(size_t)r * KP1 + DDIM] = h;
        g_x_lo[(size_t)r * KP1 + DDIM] = l;
        g_x_hi[(size_t)(r + 8) * KP1 + DDIM] = h;
        g_x_lo[(size_t)(r + 8) * KP1 + DDIM] = l;
    }
}

// ---------------- host launcher ----------------
extern "C" void kernel_launch(void* const* d_in, const int* in_sizes, int n_in,
                              void* d_out, int out_size) {
    const float* theta0  = (const float*)d_in[0];
    const float* context = (const float*)d_in[1];
    const float* W1      = (const float*)d_in[2];
    const float* b1      = (const float*)d_in[3];
    const float* W2      = (const float*)d_in[4];
    const float* b2      = (const float*)d_in[5];
    const float* W3      = (const float*)d_in[6];
    const float* b3      = (const float*)d_in[7];
    float* out = (float*)d_out;

    __nv_bfloat16 *xh, *xl, *h1h, *h1l, *h2h, *h2l, *b1h, *b1l, *b2h, *b2l;
    cudaGetSymbolAddress((void**)&xh,  g_x_hi);
    cudaGetSymbolAddress((void**)&xl,  g_x_lo);
    cudaGetSymbolAddress((void**)&h1h, g_h1_hi);
    cudaGetSymbolAddress((void**)&h1l, g_h1_lo);
    cudaGetSymbolAddress((void**)&h2h, g_h2_hi);
    cudaGetSymbolAddress((void**)&h2l, g_h2_lo);
    cudaGetSymbolAddress((void**)&b1h, g_B1_hi);
    cudaGetSymbolAddress((void**)&b1l, g_B1_lo);
    cudaGetSymbolAddress((void**)&b2h, g_B2_hi);
    cudaGetSymbolAddress((void**)&b2l, g_B2_lo);

    cudaFuncSetAttribute(glu_mma, cudaFuncAttributeMaxDynamicSharedMemorySize, GLU_SMEM);
    cudaFuncSetAttribute(k3_mma,  cudaFuncAttributeMaxDynamicSharedMemorySize, K3_SMEM);

    init_wt<<<(1024 * KP1 + 255) / 256, 256>>>(W1, INRAW, KP1, b1h, b1l);
    init_wt<<<(1024 * KP2 + 255) / 256, 256>>>(W2, KP2,   KP2, b2h, b2l);
    init_w3t<<<(DDIM * HID + 255) / 256, 256>>>(W3);
    init_x<<<BATCH, KP1>>>(theta0, context);

    const float dt = 1.0f / NSTEPS;
    dim3 ggrid(HID / 64, BATCH / 128);   // (8, 16)

    for (int i = 0; i < NSTEPS; ++i) {
        float t0 = (float)i * dt;
        for (int s = 0; s < 4; ++s) {
            glu_mma<<<ggrid, 256, GLU_SMEM>>>(xh, xl, KP1, KP1 / 64, b1h, b1l, KP1,
                                              b1, h1h, h1l);
            glu_mma<<<ggrid, 256, GLU_SMEM>>>(h1h, h1l, KP2, KP2 / 64, b2h, b2l, KP2,
                                              b2, h2h, h2l);
            float t_next = (s <= 1) ? (t0 + 0.5f * dt) : (t0 + dt);
            bool last = (i == NSTEPS - 1) && (s == 3);
            k3_mma<<<BATCH / 64, 128, K3_SMEM>>>(b3, s, t_next, dt,
                                                 last ? out : nullptr);
        }
    }
}